// round 4
// baseline (speedup 1.0000x reference)
#include <cuda_runtime.h>
#include <math.h>

#define SEQ    2048
#define HID    2048
#define NH     16
#define HD     128
#define BATCH  2
#define WIN    256

// ---------------- scratch (static device globals; no allocations) -----------
__device__ float  g_Q[BATCH*NH*SEQ*HD];      // [B,H,S,D]
__device__ float  g_K[BATCH*NH*SEQ*HD];
__device__ float  g_V[BATCH*NH*SEQ*HD];
__device__ float  g_attn[BATCH*SEQ*NH*HD];   // [B,S,H*D]
__device__ float2 g_rope[SEQ*64];            // cos/sin table

// ---------------- RoPE table (match reference f32 angle, accurate trig) -----
__global__ void rope_tab_kernel() {
    int idx = blockIdx.x * blockDim.x + threadIdx.x;
    if (idx >= SEQ * 64) return;
    int s = idx >> 6, j = idx & 63;
    float invf = (float)pow(10000.0, -(double)j / 64.0); // f32-rounded like ref
    float ang  = (float)s * invf;                        // f32 product like ref
    double a   = (double)ang;
    g_rope[idx] = make_float2((float)cos(a), (float)sin(a));
}

// ---------------- fused QKV GEMM (+bias, +RoPE for Q/K, BHSD epilogue) ------
// C(M=4096,N=2048) = x(4096x2048) @ W(2048x2048); blockIdx.z selects Q/K/V.
__global__ __launch_bounds__(256, 2) void qkv_gemm_kernel(
    const float* __restrict__ x,
    const float* __restrict__ WQ, const float* __restrict__ bQ,
    const float* __restrict__ WK, const float* __restrict__ bK,
    const float* __restrict__ WV, const float* __restrict__ bV)
{
    __shared__ float As[16][129];   // transposed A tile, padded
    __shared__ float Bs[16][128];

    const int z = blockIdx.z;
    const float* __restrict__ W    = (z == 0) ? WQ : ((z == 1) ? WK : WV);
    const float* __restrict__ bias = (z == 0) ? bQ : ((z == 1) ? bK : bV);

    const int tid = threadIdx.x;
    const int tx = tid & 15, ty = tid >> 4;
    const int m0 = blockIdx.y * 128, n0 = blockIdx.x * 128;

    const int aRow = tid >> 2, aCol = (tid & 3) * 4;
    const int bRow = tid >> 5, bCol = (tid & 31) * 4;

    const float* Ab = x + (m0 + aRow) * HID + aCol;
    const float* Bb = W + bRow * HID + n0 + bCol;

    float4 a0 = *(const float4*)(Ab);
    float4 a1 = *(const float4*)(Ab + 64 * HID);
    float4 b0 = *(const float4*)(Bb);
    float4 b1 = *(const float4*)(Bb + 8 * HID);

    float acc[8][8];
    #pragma unroll
    for (int i = 0; i < 8; i++)
        #pragma unroll
        for (int j = 0; j < 8; j++) acc[i][j] = 0.f;

    const int NT = HID / 16;
    for (int kt = 0; kt < NT; kt++) {
        As[aCol+0][aRow]    = a0.x; As[aCol+1][aRow]    = a0.y;
        As[aCol+2][aRow]    = a0.z; As[aCol+3][aRow]    = a0.w;
        As[aCol+0][aRow+64] = a1.x; As[aCol+1][aRow+64] = a1.y;
        As[aCol+2][aRow+64] = a1.z; As[aCol+3][aRow+64] = a1.w;
        *(float4*)&Bs[bRow][bCol]   = b0;
        *(float4*)&Bs[bRow+8][bCol] = b1;
        __syncthreads();
        if (kt + 1 < NT) {
            const float* Ap = Ab + (kt + 1) * 16;
            a0 = *(const float4*)(Ap);
            a1 = *(const float4*)(Ap + 64 * HID);
            const float* Bp = Bb + (kt + 1) * 16 * HID;
            b0 = *(const float4*)(Bp);
            b1 = *(const float4*)(Bp + 8 * HID);
        }
        #pragma unroll
        for (int k = 0; k < 16; k++) {
            float ra[8], rb[8];
            #pragma unroll
            for (int i = 0; i < 8; i++) ra[i] = As[k][ty + 16 * i];
            #pragma unroll
            for (int j = 0; j < 8; j++) rb[j] = Bs[k][tx + 16 * j];
            #pragma unroll
            for (int i = 0; i < 8; i++)
                #pragma unroll
                for (int j = 0; j < 8; j++)
                    acc[i][j] = fmaf(ra[i], rb[j], acc[i][j]);
        }
        __syncthreads();
    }

    float bv[8];
    #pragma unroll
    for (int j = 0; j < 8; j++) bv[j] = bias[n0 + tx + 16 * j];

    const int h = blockIdx.x;  // BN==HD so the n-tile is exactly one head
    float* out = (z == 0) ? g_Q : ((z == 1) ? g_K : g_V);

    #pragma unroll
    for (int i = 0; i < 8; i++) {
        int r  = m0 + ty + 16 * i;
        int bb = r >> 11;
        int s  = r & (SEQ - 1);
        float* orow = out + ((size_t)(bb * NH + h) * SEQ + s) * HD;
        if (z < 2) {
            // RoPE: cols tx+16j pair (d, d+64) within the same thread (j<->j+4)
            #pragma unroll
            for (int j = 0; j < 4; j++) {
                int d1 = tx + 16 * j;                 // < 64
                float t1 = acc[i][j]     + bv[j];
                float t2 = acc[i][j + 4] + bv[j + 4];
                float2 cs = g_rope[s * 64 + d1];
                orow[d1]      = t1 * cs.x - t2 * cs.y;
                orow[d1 + 64] = t1 * cs.y + t2 * cs.x;
            }
        } else {
            #pragma unroll
            for (int j = 0; j < 8; j++) orow[tx + 16 * j] = acc[i][j] + bv[j];
        }
    }
}

// ---------------- sliding-window flash attention ----------------------------
// block = (64 queries) x (b,h). 256 threads as 16x16: rows ty*4+i, cols tx+16*j.
#define QS_OFF 0
#define VS_OFF 8192
#define KS_OFF 16384            // 64 x 33
#define PS_OFF 18496            // 64 x 65
#define ATT_SMEM_BYTES ((18496 + 64*65) * 4)   // 22656 floats = 90624 B

__global__ __launch_bounds__(256) void attn_kernel(const float* __restrict__ kw) {
    extern __shared__ float sm[];
    float* Qs = sm + QS_OFF;
    float* Vs = sm + VS_OFF;
    float* Ks = sm + KS_OFF;
    float* Ps = sm + PS_OFF;

    const int tid = threadIdx.x;
    const int tx = tid & 15, ty = tid >> 4;
    const int q0 = blockIdx.x * 64;
    const int h  = blockIdx.y, b = blockIdx.z;

    const size_t base = (size_t)(b * NH + h) * SEQ * HD;
    const float* Qg = g_Q + base + (size_t)q0 * HD;
    const float* Kg = g_K + base;
    const float* Vg = g_V + base;

    #pragma unroll
    for (int t = 0; t < 8; t++) {
        int f = tid + t * 256;
        *(float4*)&Qs[f * 4] = *(const float4*)&Qg[f * 4];
    }

    const float mult = 0.08838834764831845f * kw[h];  // 1/sqrt(128) * key_weight

    float O[4][8];
    #pragma unroll
    for (int i = 0; i < 4; i++)
        #pragma unroll
        for (int j = 0; j < 8; j++) O[i][j] = 0.f;
    float mrow[4], lrow[4];
    #pragma unroll
    for (int i = 0; i < 4; i++) { mrow[i] = -1e30f; lrow[i] = 0.f; }

    const int kt_lo = (q0 >= WIN) ? ((q0 - WIN) >> 6) : 0;
    const int kt_hi = q0 >> 6;

    for (int kt = kt_lo; kt <= kt_hi; kt++) {
        const int k0 = kt * 64;
        __syncthreads();                         // prev tile's Ps/Vs fully consumed
        #pragma unroll
        for (int t = 0; t < 8; t++) {            // V tile 64x128
            int f = tid + t * 256;
            *(float4*)&Vs[f * 4] = *(const float4*)&Vg[(size_t)k0 * HD + f * 4];
        }

        float S[4][4];
        #pragma unroll
        for (int i = 0; i < 4; i++)
            #pragma unroll
            for (int jj = 0; jj < 4; jj++) S[i][jj] = 0.f;

        #pragma unroll
        for (int dc = 0; dc < 4; dc++) {         // K chunks of 32 dims
            #pragma unroll
            for (int t = 0; t < 2; t++) {
                int f = tid + t * 256;
                int r = f >> 3, c4 = (f & 7) * 4;
                float4 v = *(const float4*)&Kg[(size_t)(k0 + r) * HD + dc * 32 + c4];
                float* kp = &Ks[r * 33 + c4];
                kp[0] = v.x; kp[1] = v.y; kp[2] = v.z; kp[3] = v.w;
            }
            __syncthreads();
            #pragma unroll
            for (int d = 0; d < 32; d++) {
                float ra[4], rb[4];
                #pragma unroll
                for (int i = 0; i < 4; i++)  ra[i]  = Qs[(ty * 4 + i) * HD + dc * 32 + d];
                #pragma unroll
                for (int jj = 0; jj < 4; jj++) rb[jj] = Ks[(tx + 16 * jj) * 33 + d];
                #pragma unroll
                for (int i = 0; i < 4; i++)
                    #pragma unroll
                    for (int jj = 0; jj < 4; jj++)
                        S[i][jj] = fmaf(ra[i], rb[jj], S[i][jj]);
            }
            __syncthreads();
        }

        // online softmax (row reductions across the 16-lane half-warp groups)
        #pragma unroll
        for (int i = 0; i < 4; i++) {
            int qi = q0 + ty * 4 + i;
            float mloc = -1e30f;
            #pragma unroll
            for (int jj = 0; jj < 4; jj++) {
                int kj = k0 + tx + 16 * jj;
                float sv = S[i][jj] * mult;
                sv = (kj <= qi && kj + WIN >= qi) ? sv : -1e30f;
                S[i][jj] = sv;
                mloc = fmaxf(mloc, sv);
            }
            #pragma unroll
            for (int msk = 8; msk >= 1; msk >>= 1)
                mloc = fmaxf(mloc, __shfl_xor_sync(0xffffffffu, mloc, msk));
            float mnew = fmaxf(mrow[i], mloc);
            float corr = expf(mrow[i] - mnew);
            float psum = 0.f;
            #pragma unroll
            for (int jj = 0; jj < 4; jj++) {
                float p = expf(S[i][jj] - mnew);
                Ps[(ty * 4 + i) * 65 + tx + 16 * jj] = p;
                psum += p;
            }
            #pragma unroll
            for (int msk = 8; msk >= 1; msk >>= 1)
                psum += __shfl_xor_sync(0xffffffffu, psum, msk);
            lrow[i] = lrow[i] * corr + psum;
            mrow[i] = mnew;
            #pragma unroll
            for (int j = 0; j < 8; j++) O[i][j] *= corr;
        }
        __syncthreads();                         // Ps (+Vs) visible

        #pragma unroll 4
        for (int k = 0; k < 64; k++) {           // O += P @ V
            float rp[4], rv[8];
            #pragma unroll
            for (int i = 0; i < 4; i++) rp[i] = Ps[(ty * 4 + i) * 65 + k];
            #pragma unroll
            for (int j = 0; j < 8; j++) rv[j] = Vs[k * HD + tx + 16 * j];
            #pragma unroll
            for (int i = 0; i < 4; i++)
                #pragma unroll
                for (int j = 0; j < 8; j++)
                    O[i][j] = fmaf(rp[i], rv[j], O[i][j]);
        }
    }

    float* Og = g_attn + (size_t)b * SEQ * HID;
    #pragma unroll
    for (int i = 0; i < 4; i++) {
        int qi = q0 + ty * 4 + i;
        float inv = 1.f / lrow[i];
        #pragma unroll
        for (int j = 0; j < 8; j++)
            Og[(size_t)qi * HID + h * HD + tx + 16 * j] = O[i][j] * inv;
    }
}

// ---------------- output projection GEMM (+bias) ----------------------------
__global__ __launch_bounds__(256, 2) void out_gemm_kernel(
    const float* __restrict__ WO, const float* __restrict__ bO,
    float* __restrict__ out)
{
    __shared__ float As[16][129];
    __shared__ float Bs[16][128];

    const float* A = g_attn;
    const int tid = threadIdx.x;
    const int tx = tid & 15, ty = tid >> 4;
    const int m0 = blockIdx.y * 128, n0 = blockIdx.x * 128;

    const int aRow = tid >> 2, aCol = (tid & 3) * 4;
    const int bRow = tid >> 5, bCol = (tid & 31) * 4;

    const float* Ab = A + (m0 + aRow) * HID + aCol;
    const float* Bb = WO + bRow * HID + n0 + bCol;

    float4 a0 = *(const float4*)(Ab);
    float4 a1 = *(const float4*)(Ab + 64 * HID);
    float4 b0 = *(const float4*)(Bb);
    float4 b1 = *(const float4*)(Bb + 8 * HID);

    float acc[8][8];
    #pragma unroll
    for (int i = 0; i < 8; i++)
        #pragma unroll
        for (int j = 0; j < 8; j++) acc[i][j] = 0.f;

    const int NT = HID / 16;
    for (int kt = 0; kt < NT; kt++) {
        As[aCol+0][aRow]    = a0.x; As[aCol+1][aRow]    = a0.y;
        As[aCol+2][aRow]    = a0.z; As[aCol+3][aRow]    = a0.w;
        As[aCol+0][aRow+64] = a1.x; As[aCol+1][aRow+64] = a1.y;
        As[aCol+2][aRow+64] = a1.z; As[aCol+3][aRow+64] = a1.w;
        *(float4*)&Bs[bRow][bCol]   = b0;
        *(float4*)&Bs[bRow+8][bCol] = b1;
        __syncthreads();
        if (kt + 1 < NT) {
            const float* Ap = Ab + (kt + 1) * 16;
            a0 = *(const float4*)(Ap);
            a1 = *(const float4*)(Ap + 64 * HID);
            const float* Bp = Bb + (kt + 1) * 16 * HID;
            b0 = *(const float4*)(Bp);
            b1 = *(const float4*)(Bp + 8 * HID);
        }
        #pragma unroll
        for (int k = 0; k < 16; k++) {
            float ra[8], rb[8];
            #pragma unroll
            for (int i = 0; i < 8; i++) ra[i] = As[k][ty + 16 * i];
            #pragma unroll
            for (int j = 0; j < 8; j++) rb[j] = Bs[k][tx + 16 * j];
            #pragma unroll
            for (int i = 0; i < 8; i++)
                #pragma unroll
                for (int j = 0; j < 8; j++)
                    acc[i][j] = fmaf(ra[i], rb[j], acc[i][j]);
        }
        __syncthreads();
    }

    float bv[8];
    #pragma unroll
    for (int j = 0; j < 8; j++) bv[j] = bO[n0 + tx + 16 * j];
    #pragma unroll
    for (int i = 0; i < 8; i++) {
        int r = m0 + ty + 16 * i;
        #pragma unroll
        for (int j = 0; j < 8; j++)
            out[(size_t)r * HID + n0 + tx + 16 * j] = acc[i][j] + bv[j];
    }
}

// ---------------- launch -----------------------------------------------------
extern "C" void kernel_launch(void* const* d_in, const int* in_sizes, int n_in,
                              void* d_out, int out_size) {
    const float* x  = (const float*)d_in[0];
    const float* WQ = (const float*)d_in[1];
    const float* bQ = (const float*)d_in[2];
    const float* WK = (const float*)d_in[3];
    const float* bK = (const float*)d_in[4];
    const float* WV = (const float*)d_in[5];
    const float* bV = (const float*)d_in[6];
    const float* WO = (const float*)d_in[7];
    const float* bO = (const float*)d_in[8];
    const float* kw = (const float*)d_in[9];
    float* out = (float*)d_out;

    rope_tab_kernel<<<(SEQ * 64 + 255) / 256, 256>>>();

    dim3 gq(HID / 128, (BATCH * SEQ) / 128, 3);
    qkv_gemm_kernel<<<gq, 256>>>(x, WQ, bQ, WK, bK, WV, bV);

    cudaFuncSetAttribute(attn_kernel, cudaFuncAttributeMaxDynamicSharedMemorySize,
                         ATT_SMEM_BYTES);
    attn_kernel<<<dim3(SEQ / 64, NH, BATCH), 256, ATT_SMEM_BYTES>>>(kw);

    out_gemm_kernel<<<dim3(HID / 128, (BATCH * SEQ) / 128), 256>>>(WO, bO, out);
}

// round 5
// speedup vs baseline: 1.8484x; 1.8484x over previous
#include <cuda_runtime.h>
#include <cuda_bf16.h>
#include <math.h>

#define SEQ    2048
#define HID    2048
#define NH     16
#define HD     128
#define BATCH  2
#define WIN    256

// ---------------- scratch (static device globals; no allocations) -----------
__device__ float  g_Q[BATCH*NH*SEQ*HD];      // [B,H,S,D]
__device__ float  g_K[BATCH*NH*SEQ*HD];
__device__ float  g_V[BATCH*NH*SEQ*HD];
__device__ float  g_attn[BATCH*SEQ*NH*HD];   // [B,S,H*D]
__device__ float2 g_rope[SEQ*64];            // cos/sin table

// ---------------- RoPE table (match reference f32 angle, accurate trig) -----
__global__ void rope_tab_kernel() {
    int idx = blockIdx.x * blockDim.x + threadIdx.x;
    if (idx >= SEQ * 64) return;
    int s = idx >> 6, j = idx & 63;
    float invf = (float)pow(10000.0, -(double)j / 64.0); // f32-rounded like ref
    float ang  = (float)s * invf;                        // f32 product like ref
    double a   = (double)ang;
    g_rope[idx] = make_float2((float)cos(a), (float)sin(a));
}

// ---------------- tensor-core helpers ---------------------------------------
__device__ __forceinline__ unsigned smem_u32(const void* p) {
    return (unsigned)__cvta_generic_to_shared(p);
}
__device__ __forceinline__ void ldsm_x4(unsigned &r0, unsigned &r1,
                                        unsigned &r2, unsigned &r3, unsigned a) {
    asm volatile("ldmatrix.sync.aligned.m8n8.x4.shared.b16 {%0,%1,%2,%3},[%4];"
                 : "=r"(r0), "=r"(r1), "=r"(r2), "=r"(r3) : "r"(a));
}
__device__ __forceinline__ void ldsm_x4_t(unsigned &r0, unsigned &r1,
                                          unsigned &r2, unsigned &r3, unsigned a) {
    asm volatile("ldmatrix.sync.aligned.m8n8.x4.trans.shared.b16 {%0,%1,%2,%3},[%4];"
                 : "=r"(r0), "=r"(r1), "=r"(r2), "=r"(r3) : "r"(a));
}
__device__ __forceinline__ void mma16816(float* c, const unsigned* a, const unsigned* b) {
    asm volatile(
        "mma.sync.aligned.m16n8k16.row.col.f32.bf16.bf16.f32 "
        "{%0,%1,%2,%3},{%4,%5,%6,%7},{%8,%9},{%0,%1,%2,%3};"
        : "+f"(c[0]), "+f"(c[1]), "+f"(c[2]), "+f"(c[3])
        : "r"(a[0]), "r"(a[1]), "r"(a[2]), "r"(a[3]), "r"(b[0]), "r"(b[1]));
}

// split 8 fp32 into bf16 hi/lo and store as two 16B chunks
__device__ __forceinline__ void split_store8(__nv_bfloat16* hp, __nv_bfloat16* lp,
                                             float4 f0, float4 f1) {
    float f[8] = {f0.x, f0.y, f0.z, f0.w, f1.x, f1.y, f1.z, f1.w};
    unsigned h[4], l[4];
    #pragma unroll
    for (int i = 0; i < 4; i++) {
        __nv_bfloat16 h0 = __float2bfloat16(f[2*i]);
        __nv_bfloat16 h1 = __float2bfloat16(f[2*i+1]);
        __nv_bfloat16 l0 = __float2bfloat16(f[2*i]   - __bfloat162float(h0));
        __nv_bfloat16 l1 = __float2bfloat16(f[2*i+1] - __bfloat162float(h1));
        __nv_bfloat162 hh = __halves2bfloat162(h0, h1);
        __nv_bfloat162 ll = __halves2bfloat162(l0, l1);
        h[i] = *(unsigned*)&hh;  l[i] = *(unsigned*)&ll;
    }
    *(uint4*)hp = make_uint4(h[0], h[1], h[2], h[3]);
    *(uint4*)lp = make_uint4(l[0], l[1], l[2], l[3]);
}

// A smem: 128 rows x 32 k, stride 40 bf16 (80B) -> conflict-free LDSM
// B smem: 32 k-rows x 128 n, stride 136 bf16 (272B) -> conflict-free LDSM.T
#define ASTR 40
#define BSTR 136

// C[128x128] = A[128xK] * B[Kx128] at (m0,n0); split-bf16 3-pass, acc fp32.
// Warp layout: 4 m-warps x 2 n-warps; warp tile 32 x 64 with interleaved
// n-tiles {0,8,16,24, 64,72,80,88}+warp_n*32 so RoPE pairs are in-thread.
__device__ __forceinline__ void tc_mainloop(
    const float* __restrict__ A, const float* __restrict__ Bm,
    int m0, int n0,
    __nv_bfloat16* sAhi, __nv_bfloat16* sAlo,
    __nv_bfloat16* sBhi, __nv_bfloat16* sBlo,
    float acc[2][8][4])
{
    const int tid = threadIdx.x;
    const int lane = tid & 31, wid = tid >> 5;
    const int warp_m = wid >> 1, warp_n = wid & 1;

    const int rA = tid >> 1, cA = (tid & 1) * 16;
    const int rB = tid >> 3, cB = (tid & 7) * 16;
    const float* Ag = A  + (size_t)(m0 + rA) * HID + cA;
    const float* Bg = Bm + (size_t)rB * HID + n0 + cB;

    float4 a0 = *(const float4*)(Ag + 0);
    float4 a1 = *(const float4*)(Ag + 4);
    float4 a2 = *(const float4*)(Ag + 8);
    float4 a3 = *(const float4*)(Ag + 12);
    float4 b0 = *(const float4*)(Bg + 0);
    float4 b1 = *(const float4*)(Bg + 4);
    float4 b2 = *(const float4*)(Bg + 8);
    float4 b3 = *(const float4*)(Bg + 12);

    const unsigned aHiB = smem_u32(sAhi), aLoB = smem_u32(sAlo);
    const unsigned bHiB = smem_u32(sBhi), bLoB = smem_u32(sBlo);
    const int arow  = warp_m * 32 + (lane & 15);
    const int acol8 = (lane >> 4) * 8;
    const int brow  = lane & 15;
    const int bcol  = warp_n * 32 + (lane >> 4) * 8;

    const int NT = HID / 32;
    for (int kt = 0; kt < NT; kt++) {
        split_store8(sAhi + rA * ASTR + cA,     sAlo + rA * ASTR + cA,     a0, a1);
        split_store8(sAhi + rA * ASTR + cA + 8, sAlo + rA * ASTR + cA + 8, a2, a3);
        split_store8(sBhi + rB * BSTR + cB,     sBlo + rB * BSTR + cB,     b0, b1);
        split_store8(sBhi + rB * BSTR + cB + 8, sBlo + rB * BSTR + cB + 8, b2, b3);
        __syncthreads();

        if (kt + 1 < NT) {
            const float* An = Ag + (kt + 1) * 32;
            a0 = *(const float4*)(An + 0);  a1 = *(const float4*)(An + 4);
            a2 = *(const float4*)(An + 8);  a3 = *(const float4*)(An + 12);
            const float* Bn = Bg + (size_t)(kt + 1) * 32 * HID;
            b0 = *(const float4*)(Bn + 0);  b1 = *(const float4*)(Bn + 4);
            b2 = *(const float4*)(Bn + 8);  b3 = *(const float4*)(Bn + 12);
        }

        #pragma unroll
        for (int kb = 0; kb < 32; kb += 16) {
            unsigned ah[2][4], al[2][4], bh[8][2], bl[8][2];
            #pragma unroll
            for (int i = 0; i < 2; i++) {
                unsigned off = (unsigned)(((arow + 16 * i) * ASTR + kb + acol8) * 2);
                ldsm_x4(ah[i][0], ah[i][1], ah[i][2], ah[i][3], aHiB + off);
                ldsm_x4(al[i][0], al[i][1], al[i][2], al[i][3], aLoB + off);
            }
            #pragma unroll
            for (int p = 0; p < 4; p++) {
                int nOff = (p & 1) * 16 + (p >> 1) * 64;
                unsigned off = (unsigned)(((kb + brow) * BSTR + bcol + nOff) * 2);
                unsigned r0, r1, r2, r3;
                ldsm_x4_t(r0, r1, r2, r3, bHiB + off);
                bh[2*p][0] = r0; bh[2*p][1] = r1; bh[2*p+1][0] = r2; bh[2*p+1][1] = r3;
                ldsm_x4_t(r0, r1, r2, r3, bLoB + off);
                bl[2*p][0] = r0; bl[2*p][1] = r1; bl[2*p+1][0] = r2; bl[2*p+1][1] = r3;
            }
            #pragma unroll
            for (int i = 0; i < 2; i++)
                #pragma unroll
                for (int j = 0; j < 8; j++) {
                    mma16816(acc[i][j], ah[i], bh[j]);   // hi*hi
                    mma16816(acc[i][j], ah[i], bl[j]);   // hi*lo
                    mma16816(acc[i][j], al[i], bh[j]);   // lo*hi
                }
        }
        __syncthreads();
    }
}

// ---------------- fused QKV GEMM (+bias, +RoPE for Q/K, BHSD epilogue) ------
__global__ __launch_bounds__(256, 1) void qkv_tc_kernel(
    const float* __restrict__ x,
    const float* __restrict__ WQ, const float* __restrict__ bQ,
    const float* __restrict__ WK, const float* __restrict__ bK,
    const float* __restrict__ WV, const float* __restrict__ bV)
{
    __shared__ __nv_bfloat16 sAhi[128*ASTR], sAlo[128*ASTR];
    __shared__ __nv_bfloat16 sBhi[32*BSTR],  sBlo[32*BSTR];

    const int z = blockIdx.z;
    const float* W    = (z == 0) ? WQ : ((z == 1) ? WK : WV);
    const float* bias = (z == 0) ? bQ : ((z == 1) ? bK : bV);
    const int m0 = blockIdx.y * 128, n0 = blockIdx.x * 128;

    float acc[2][8][4];
    #pragma unroll
    for (int i = 0; i < 2; i++)
        #pragma unroll
        for (int j = 0; j < 8; j++)
            #pragma unroll
            for (int r = 0; r < 4; r++) acc[i][j][r] = 0.f;

    tc_mainloop(x, W, m0, n0, sAhi, sAlo, sBhi, sBlo, acc);

    const int tid = threadIdx.x, lane = tid & 31, wid = tid >> 5;
    const int warp_m = wid >> 1, warp_n = wid & 1;
    const int g = lane >> 2, c = lane & 3;
    const int wb = warp_n * 32;
    const int h = blockIdx.x;                 // N-tile == one head
    float* out = (z == 0) ? g_Q : ((z == 1) ? g_K : g_V);

    #pragma unroll
    for (int i = 0; i < 2; i++) {
        #pragma unroll
        for (int rh = 0; rh < 2; rh++) {
            int rm = m0 + warp_m * 32 + 16 * i + g + 8 * rh;
            int bb = rm >> 11, s = rm & (SEQ - 1);
            float* orow = out + ((size_t)(bb * NH + h) * SEQ + s) * HD;
            if (z < 2) {
                #pragma unroll
                for (int j = 0; j < 4; j++) {
                    #pragma unroll
                    for (int d = 0; d < 2; d++) {
                        int reg = rh * 2 + d;
                        int d1  = wb + 8 * j + 2 * c + d;       // < 64
                        float t1 = acc[i][j][reg]     + bias[n0 + d1];
                        float t2 = acc[i][j + 4][reg] + bias[n0 + d1 + 64];
                        float2 cs = g_rope[s * 64 + d1];
                        orow[d1]      = t1 * cs.x - t2 * cs.y;
                        orow[d1 + 64] = t1 * cs.y + t2 * cs.x;
                    }
                }
            } else {
                #pragma unroll
                for (int j = 0; j < 8; j++) {
                    #pragma unroll
                    for (int d = 0; d < 2; d++) {
                        int col = wb + (j & 3) * 8 + (j >> 2) * 64 + 2 * c + d;
                        orow[col] = acc[i][j][rh * 2 + d] + bias[n0 + col];
                    }
                }
            }
        }
    }
}

// ---------------- output projection GEMM (+bias) ----------------------------
__global__ __launch_bounds__(256, 1) void out_tc_kernel(
    const float* __restrict__ WO, const float* __restrict__ bO,
    float* __restrict__ out)
{
    __shared__ __nv_bfloat16 sAhi[128*ASTR], sAlo[128*ASTR];
    __shared__ __nv_bfloat16 sBhi[32*BSTR],  sBlo[32*BSTR];

    const int m0 = blockIdx.y * 128, n0 = blockIdx.x * 128;

    float acc[2][8][4];
    #pragma unroll
    for (int i = 0; i < 2; i++)
        #pragma unroll
        for (int j = 0; j < 8; j++)
            #pragma unroll
            for (int r = 0; r < 4; r++) acc[i][j][r] = 0.f;

    tc_mainloop(g_attn, WO, m0, n0, sAhi, sAlo, sBhi, sBlo, acc);

    const int tid = threadIdx.x, lane = tid & 31, wid = tid >> 5;
    const int warp_m = wid >> 1, warp_n = wid & 1;
    const int g = lane >> 2, c = lane & 3;
    const int wb = warp_n * 32;

    #pragma unroll
    for (int i = 0; i < 2; i++) {
        #pragma unroll
        for (int rh = 0; rh < 2; rh++) {
            int rm = m0 + warp_m * 32 + 16 * i + g + 8 * rh;
            #pragma unroll
            for (int j = 0; j < 8; j++) {
                #pragma unroll
                for (int d = 0; d < 2; d++) {
                    int col = n0 + wb + (j & 3) * 8 + (j >> 2) * 64 + 2 * c + d;
                    out[(size_t)rm * HID + col] = acc[i][j][rh * 2 + d] + bO[col];
                }
            }
        }
    }
}

// ---------------- sliding-window flash attention (unchanged) ----------------
#define QS_OFF 0
#define VS_OFF 8192
#define KS_OFF 16384            // 64 x 33
#define PS_OFF 18496            // 64 x 65
#define ATT_SMEM_BYTES ((18496 + 64*65) * 4)

__global__ __launch_bounds__(256) void attn_kernel(const float* __restrict__ kw) {
    extern __shared__ float sm[];
    float* Qs = sm + QS_OFF;
    float* Vs = sm + VS_OFF;
    float* Ks = sm + KS_OFF;
    float* Ps = sm + PS_OFF;

    const int tid = threadIdx.x;
    const int tx = tid & 15, ty = tid >> 4;
    const int q0 = blockIdx.x * 64;
    const int h  = blockIdx.y, b = blockIdx.z;

    const size_t base = (size_t)(b * NH + h) * SEQ * HD;
    const float* Qg = g_Q + base + (size_t)q0 * HD;
    const float* Kg = g_K + base;
    const float* Vg = g_V + base;

    #pragma unroll
    for (int t = 0; t < 8; t++) {
        int f = tid + t * 256;
        *(float4*)&Qs[f * 4] = *(const float4*)&Qg[f * 4];
    }

    const float mult = 0.08838834764831845f * kw[h];

    float O[4][8];
    #pragma unroll
    for (int i = 0; i < 4; i++)
        #pragma unroll
        for (int j = 0; j < 8; j++) O[i][j] = 0.f;
    float mrow[4], lrow[4];
    #pragma unroll
    for (int i = 0; i < 4; i++) { mrow[i] = -1e30f; lrow[i] = 0.f; }

    const int kt_lo = (q0 >= WIN) ? ((q0 - WIN) >> 6) : 0;
    const int kt_hi = q0 >> 6;

    for (int kt = kt_lo; kt <= kt_hi; kt++) {
        const int k0 = kt * 64;
        __syncthreads();
        #pragma unroll
        for (int t = 0; t < 8; t++) {
            int f = tid + t * 256;
            *(float4*)&Vs[f * 4] = *(const float4*)&Vg[(size_t)k0 * HD + f * 4];
        }

        float S[4][4];
        #pragma unroll
        for (int i = 0; i < 4; i++)
            #pragma unroll
            for (int jj = 0; jj < 4; jj++) S[i][jj] = 0.f;

        #pragma unroll
        for (int dc = 0; dc < 4; dc++) {
            #pragma unroll
            for (int t = 0; t < 2; t++) {
                int f = tid + t * 256;
                int r = f >> 3, c4 = (f & 7) * 4;
                float4 v = *(const float4*)&Kg[(size_t)(k0 + r) * HD + dc * 32 + c4];
                float* kp = &Ks[r * 33 + c4];
                kp[0] = v.x; kp[1] = v.y; kp[2] = v.z; kp[3] = v.w;
            }
            __syncthreads();
            #pragma unroll
            for (int d = 0; d < 32; d++) {
                float ra[4], rb[4];
                #pragma unroll
                for (int i = 0; i < 4; i++)  ra[i]  = Qs[(ty * 4 + i) * HD + dc * 32 + d];
                #pragma unroll
                for (int jj = 0; jj < 4; jj++) rb[jj] = Ks[(tx + 16 * jj) * 33 + d];
                #pragma unroll
                for (int i = 0; i < 4; i++)
                    #pragma unroll
                    for (int jj = 0; jj < 4; jj++)
                        S[i][jj] = fmaf(ra[i], rb[jj], S[i][jj]);
            }
            __syncthreads();
        }

        #pragma unroll
        for (int i = 0; i < 4; i++) {
            int qi = q0 + ty * 4 + i;
            float mloc = -1e30f;
            #pragma unroll
            for (int jj = 0; jj < 4; jj++) {
                int kj = k0 + tx + 16 * jj;
                float sv = S[i][jj] * mult;
                sv = (kj <= qi && kj + WIN >= qi) ? sv : -1e30f;
                S[i][jj] = sv;
                mloc = fmaxf(mloc, sv);
            }
            #pragma unroll
            for (int msk = 8; msk >= 1; msk >>= 1)
                mloc = fmaxf(mloc, __shfl_xor_sync(0xffffffffu, mloc, msk));
            float mnew = fmaxf(mrow[i], mloc);
            float corr = expf(mrow[i] - mnew);
            float psum = 0.f;
            #pragma unroll
            for (int jj = 0; jj < 4; jj++) {
                float p = expf(S[i][jj] - mnew);
                Ps[(ty * 4 + i) * 65 + tx + 16 * jj] = p;
                psum += p;
            }
            #pragma unroll
            for (int msk = 8; msk >= 1; msk >>= 1)
                psum += __shfl_xor_sync(0xffffffffu, psum, msk);
            lrow[i] = lrow[i] * corr + psum;
            mrow[i] = mnew;
            #pragma unroll
            for (int j = 0; j < 8; j++) O[i][j] *= corr;
        }
        __syncthreads();

        #pragma unroll 4
        for (int k = 0; k < 64; k++) {
            float rp[4], rv[8];
            #pragma unroll
            for (int i = 0; i < 4; i++) rp[i] = Ps[(ty * 4 + i) * 65 + k];
            #pragma unroll
            for (int j = 0; j < 8; j++) rv[j] = Vs[k * HD + tx + 16 * j];
            #pragma unroll
            for (int i = 0; i < 4; i++)
                #pragma unroll
                for (int j = 0; j < 8; j++)
                    O[i][j] = fmaf(rp[i], rv[j], O[i][j]);
        }
    }

    float* Og = g_attn + (size_t)b * SEQ * HID;
    #pragma unroll
    for (int i = 0; i < 4; i++) {
        int qi = q0 + ty * 4 + i;
        float inv = 1.f / lrow[i];
        #pragma unroll
        for (int j = 0; j < 8; j++)
            Og[(size_t)qi * HID + h * HD + tx + 16 * j] = O[i][j] * inv;
    }
}

// ---------------- launch -----------------------------------------------------
extern "C" void kernel_launch(void* const* d_in, const int* in_sizes, int n_in,
                              void* d_out, int out_size) {
    const float* x  = (const float*)d_in[0];
    const float* WQ = (const float*)d_in[1];
    const float* bQ = (const float*)d_in[2];
    const float* WK = (const float*)d_in[3];
    const float* bK = (const float*)d_in[4];
    const float* WV = (const float*)d_in[5];
    const float* bV = (const float*)d_in[6];
    const float* WO = (const float*)d_in[7];
    const float* bO = (const float*)d_in[8];
    const float* kw = (const float*)d_in[9];
    float* out = (float*)d_out;

    rope_tab_kernel<<<(SEQ * 64 + 255) / 256, 256>>>();

    dim3 gq(NH, (BATCH * SEQ) / 128, 3);
    qkv_tc_kernel<<<gq, 256>>>(x, WQ, bQ, WK, bK, WV, bV);

    cudaFuncSetAttribute(attn_kernel, cudaFuncAttributeMaxDynamicSharedMemorySize,
                         ATT_SMEM_BYTES);
    attn_kernel<<<dim3(SEQ / 64, NH, BATCH), 256, ATT_SMEM_BYTES>>>(kw);

    out_tc_kernel<<<dim3(HID / 128, (BATCH * SEQ) / 128), 256>>>(WO, bO, out);
}

// round 7
// speedup vs baseline: 2.0612x; 1.1151x over previous
#include <cuda_runtime.h>
#include <cuda_bf16.h>
#include <math.h>

#define SEQ    2048
#define HID    2048
#define NH     16
#define HD     128
#define BATCH  2
#define WIN    256
#define MTOT   (BATCH*SEQ)

// ---------------- scratch (static device globals; no allocations) -----------
__device__ float  g_Q[BATCH*NH*SEQ*HD];      // [B,H,S,D]
__device__ float  g_K[BATCH*NH*SEQ*HD];
__device__ float  g_V[BATCH*NH*SEQ*HD];
__device__ __nv_bfloat16 g_xhi[MTOT*HID], g_xlo[MTOT*HID];     // split x
__device__ __nv_bfloat16 g_Whi[4*HID*HID], g_Wlo[4*HID*HID];   // split Q,K,V,O weights
__device__ __nv_bfloat16 g_ahi[MTOT*HID], g_alo[MTOT*HID];     // split attn output
__device__ float2 g_rope[SEQ*64];            // cos/sin table

// ---------------- RoPE table (match reference f32 angle, accurate trig) -----
__global__ void rope_tab_kernel() {
    int idx = blockIdx.x * blockDim.x + threadIdx.x;
    if (idx >= SEQ * 64) return;
    int s = idx >> 6, j = idx & 63;
    float invf = (float)pow(10000.0, -(double)j / 64.0);
    float ang  = (float)s * invf;
    double a   = (double)ang;
    g_rope[idx] = make_float2((float)cos(a), (float)sin(a));
}

// ---------------- fp32 -> bf16 hi/lo split ----------------------------------
__global__ void split_kernel(const float* __restrict__ in,
                             __nv_bfloat16* __restrict__ hi,
                             __nv_bfloat16* __restrict__ lo, int n4) {
    int i = blockIdx.x * blockDim.x + threadIdx.x;
    if (i >= n4) return;
    float4 f = ((const float4*)in)[i];
    float v[4] = {f.x, f.y, f.z, f.w};
    unsigned h[2], l[2];
    #pragma unroll
    for (int p = 0; p < 2; p++) {
        __nv_bfloat16 h0 = __float2bfloat16(v[2*p]);
        __nv_bfloat16 h1 = __float2bfloat16(v[2*p+1]);
        __nv_bfloat16 l0 = __float2bfloat16(v[2*p]   - __bfloat162float(h0));
        __nv_bfloat16 l1 = __float2bfloat16(v[2*p+1] - __bfloat162float(h1));
        __nv_bfloat162 hh = __halves2bfloat162(h0, h1);
        __nv_bfloat162 ll = __halves2bfloat162(l0, l1);
        h[p] = *(unsigned*)&hh; l[p] = *(unsigned*)&ll;
    }
    *(uint2*)(hi + 4 * (size_t)i) = make_uint2(h[0], h[1]);
    *(uint2*)(lo + 4 * (size_t)i) = make_uint2(l[0], l[1]);
}

// ---------------- tensor-core helpers ---------------------------------------
__device__ __forceinline__ unsigned smem_u32(const void* p) {
    return (unsigned)__cvta_generic_to_shared(p);
}
__device__ __forceinline__ void ldsm_x4(unsigned &r0, unsigned &r1,
                                        unsigned &r2, unsigned &r3, unsigned a) {
    asm volatile("ldmatrix.sync.aligned.m8n8.x4.shared.b16 {%0,%1,%2,%3},[%4];"
                 : "=r"(r0), "=r"(r1), "=r"(r2), "=r"(r3) : "r"(a));
}
__device__ __forceinline__ void ldsm_x4_t(unsigned &r0, unsigned &r1,
                                          unsigned &r2, unsigned &r3, unsigned a) {
    asm volatile("ldmatrix.sync.aligned.m8n8.x4.trans.shared.b16 {%0,%1,%2,%3},[%4];"
                 : "=r"(r0), "=r"(r1), "=r"(r2), "=r"(r3) : "r"(a));
}
__device__ __forceinline__ void mma16816(float* c, const unsigned* a, const unsigned* b) {
    asm volatile(
        "mma.sync.aligned.m16n8k16.row.col.f32.bf16.bf16.f32 "
        "{%0,%1,%2,%3},{%4,%5,%6,%7},{%8,%9},{%0,%1,%2,%3};"
        : "+f"(c[0]), "+f"(c[1]), "+f"(c[2]), "+f"(c[3])
        : "r"(a[0]), "r"(a[1]), "r"(a[2]), "r"(a[3]), "r"(b[0]), "r"(b[1]));
}
__device__ __forceinline__ void cp16(unsigned s, const void* g) {
    asm volatile("cp.async.cg.shared.global [%0], [%1], 16;" :: "r"(s), "l"(g));
}
__device__ __forceinline__ void cp_commit() {
    asm volatile("cp.async.commit_group;");
}
__device__ __forceinline__ void cp_wait1() {
    asm volatile("cp.async.wait_group 1;");
}

// smem geometry (bf16 units); conflict-free for LDSM / LDSM.T
#define ASTR 40                 // 128 rows x 32 k, 80B rows
#define BSTR 136                // 32 k-rows x 128 n, 272B rows
#define STAGES 3
#define A_ONE   (128*ASTR)      // one matrix (hi or lo)
#define A_STAGE (2*A_ONE)
#define B_ONE   (32*BSTR)
#define B_STAGE (2*B_ONE)
#define B_BASE  (STAGES*A_STAGE)
#define GEMM_SMEM_BF16 (B_BASE + STAGES*B_STAGE)
#define GEMM_SMEM_BYTES (GEMM_SMEM_BF16*2)

// C[128x128] = A[128xK] * B[Kx128]; split-bf16 3-pass, fp32 accumulate.
// 4 m-warps x 2 n-warps; warp tile 32x64, n-tiles {0,8,16,24}∪{64..88}+wn*32.
__device__ __forceinline__ void tc_mainloop(
    const __nv_bfloat16* __restrict__ Ahi_g, const __nv_bfloat16* __restrict__ Alo_g,
    const __nv_bfloat16* __restrict__ Bhi_g, const __nv_bfloat16* __restrict__ Blo_g,
    int m0, int n0, __nv_bfloat16* sm, float acc[2][8][4])
{
    const int tid = threadIdx.x;
    const int lane = tid & 31, wid = tid >> 5;
    const int warp_m = wid >> 1, warp_n = wid & 1;
    const unsigned smB = smem_u32(sm);

    // per-thread cp.async coords: 2 chunks of 16B per matrix per stage
    const int c0 = tid, c1 = tid + 256;
    const int aR0 = c0 >> 2, aC0 = (c0 & 3) * 8;
    const int aR1 = c1 >> 2, aC1 = (c1 & 3) * 8;
    const int bR0 = c0 >> 4, bC0 = (c0 & 15) * 8;
    const int bR1 = c1 >> 4, bC1 = (c1 & 15) * 8;

    const int NT = HID / 32;

    auto issue = [&](int slot, int kt) {
        unsigned sa = smB + (slot * A_STAGE) * 2;
        unsigned sb = smB + (B_BASE + slot * B_STAGE) * 2;
        const __nv_bfloat16* Ah = Ahi_g + (size_t)m0 * HID + kt * 32;
        const __nv_bfloat16* Al = Alo_g + (size_t)m0 * HID + kt * 32;
        const __nv_bfloat16* Bh = Bhi_g + (size_t)(kt * 32) * HID + n0;
        const __nv_bfloat16* Bl = Blo_g + (size_t)(kt * 32) * HID + n0;
        cp16(sa + (aR0 * ASTR + aC0) * 2,           Ah + (size_t)aR0 * HID + aC0);
        cp16(sa + (aR1 * ASTR + aC1) * 2,           Ah + (size_t)aR1 * HID + aC1);
        cp16(sa + (A_ONE + aR0 * ASTR + aC0) * 2,   Al + (size_t)aR0 * HID + aC0);
        cp16(sa + (A_ONE + aR1 * ASTR + aC1) * 2,   Al + (size_t)aR1 * HID + aC1);
        cp16(sb + (bR0 * BSTR + bC0) * 2,           Bh + (size_t)bR0 * HID + bC0);
        cp16(sb + (bR1 * BSTR + bC1) * 2,           Bh + (size_t)bR1 * HID + bC1);
        cp16(sb + (B_ONE + bR0 * BSTR + bC0) * 2,   Bl + (size_t)bR0 * HID + bC0);
        cp16(sb + (B_ONE + bR1 * BSTR + bC1) * 2,   Bl + (size_t)bR1 * HID + bC1);
    };

    const int arow  = warp_m * 32 + (lane & 15);
    const int acol8 = (lane >> 4) * 8;
    const int brow  = lane & 15;
    const int bcol  = warp_n * 32 + (lane >> 4) * 8;

    // prologue: stages 0..STAGES-2
    #pragma unroll
    for (int s = 0; s < STAGES - 1; s++) { issue(s, s); cp_commit(); }

    for (int kt = 0; kt < NT; kt++) {
        cp_wait1();
        __syncthreads();
        if (kt + STAGES - 1 < NT) issue((kt + STAGES - 1) % STAGES, kt + STAGES - 1);
        cp_commit();

        const int slot = kt % STAGES;
        unsigned aHiB = smB + (slot * A_STAGE) * 2;
        unsigned aLoB = aHiB + A_ONE * 2;
        unsigned bHiB = smB + (B_BASE + slot * B_STAGE) * 2;
        unsigned bLoB = bHiB + B_ONE * 2;

        #pragma unroll
        for (int kb = 0; kb < 32; kb += 16) {
            unsigned ah[2][4], al[2][4], bh[8][2], bl[8][2];
            #pragma unroll
            for (int i = 0; i < 2; i++) {
                unsigned off = (unsigned)(((arow + 16 * i) * ASTR + kb + acol8) * 2);
                ldsm_x4(ah[i][0], ah[i][1], ah[i][2], ah[i][3], aHiB + off);
                ldsm_x4(al[i][0], al[i][1], al[i][2], al[i][3], aLoB + off);
            }
            #pragma unroll
            for (int p = 0; p < 4; p++) {
                int nOff = (p & 1) * 16 + (p >> 1) * 64;
                unsigned off = (unsigned)(((kb + brow) * BSTR + bcol + nOff) * 2);
                unsigned r0, r1, r2, r3;
                ldsm_x4_t(r0, r1, r2, r3, bHiB + off);
                bh[2*p][0] = r0; bh[2*p][1] = r1; bh[2*p+1][0] = r2; bh[2*p+1][1] = r3;
                ldsm_x4_t(r0, r1, r2, r3, bLoB + off);
                bl[2*p][0] = r0; bl[2*p][1] = r1; bl[2*p+1][0] = r2; bl[2*p+1][1] = r3;
            }
            #pragma unroll
            for (int i = 0; i < 2; i++)
                #pragma unroll
                for (int j = 0; j < 8; j++) {
                    mma16816(acc[i][j], ah[i], bh[j]);
                    mma16816(acc[i][j], ah[i], bl[j]);
                    mma16816(acc[i][j], al[i], bh[j]);
                }
        }
        __syncthreads();
    }
}

// ---------------- fused QKV GEMM (+bias, +RoPE for Q/K, BHSD epilogue) ------
__global__ __launch_bounds__(256, 1) void qkv_tc_kernel(
    const float* __restrict__ bQ, const float* __restrict__ bK,
    const float* __restrict__ bV)
{
    extern __shared__ __align__(16) __nv_bfloat16 smg[];
    const int z = blockIdx.z;
    const float* bias = (z == 0) ? bQ : ((z == 1) ? bK : bV);
    const int m0 = blockIdx.y * 128, n0 = blockIdx.x * 128;

    float acc[2][8][4];
    #pragma unroll
    for (int i = 0; i < 2; i++)
        #pragma unroll
        for (int j = 0; j < 8; j++)
            #pragma unroll
            for (int r = 0; r < 4; r++) acc[i][j][r] = 0.f;

    const size_t wz = (size_t)z * HID * HID;
    tc_mainloop(g_xhi, g_xlo, g_Whi + wz, g_Wlo + wz, m0, n0, smg, acc);

    const int tid = threadIdx.x, lane = tid & 31, wid = tid >> 5;
    const int warp_m = wid >> 1, warp_n = wid & 1;
    const int g = lane >> 2, c = lane & 3;
    const int wb = warp_n * 32;
    const int h = blockIdx.x;                 // N-tile == one head
    float* out = (z == 0) ? g_Q : ((z == 1) ? g_K : g_V);

    #pragma unroll
    for (int i = 0; i < 2; i++) {
        #pragma unroll
        for (int rh = 0; rh < 2; rh++) {
            int rm = m0 + warp_m * 32 + 16 * i + g + 8 * rh;
            int bb = rm >> 11, s = rm & (SEQ - 1);
            float* orow = out + ((size_t)(bb * NH + h) * SEQ + s) * HD;
            if (z < 2) {
                #pragma unroll
                for (int j = 0; j < 4; j++) {
                    #pragma unroll
                    for (int d = 0; d < 2; d++) {
                        int reg = rh * 2 + d;
                        int d1  = wb + 8 * j + 2 * c + d;       // < 64
                        float t1 = acc[i][j][reg]     + bias[n0 + d1];
                        float t2 = acc[i][j + 4][reg] + bias[n0 + d1 + 64];
                        float2 cs = g_rope[s * 64 + d1];
                        orow[d1]      = t1 * cs.x - t2 * cs.y;
                        orow[d1 + 64] = t1 * cs.y + t2 * cs.x;
                    }
                }
            } else {
                #pragma unroll
                for (int j = 0; j < 8; j++) {
                    #pragma unroll
                    for (int d = 0; d < 2; d++) {
                        int col = wb + (j & 3) * 8 + (j >> 2) * 64 + 2 * c + d;
                        orow[col] = acc[i][j][rh * 2 + d] + bias[n0 + col];
                    }
                }
            }
        }
    }
}

// ---------------- output projection GEMM (+bias) ----------------------------
__global__ __launch_bounds__(256, 1) void out_tc_kernel(
    const float* __restrict__ bO, float* __restrict__ out)
{
    extern __shared__ __align__(16) __nv_bfloat16 smg[];
    const int m0 = blockIdx.y * 128, n0 = blockIdx.x * 128;

    float acc[2][8][4];
    #pragma unroll
    for (int i = 0; i < 2; i++)
        #pragma unroll
        for (int j = 0; j < 8; j++)
            #pragma unroll
            for (int r = 0; r < 4; r++) acc[i][j][r] = 0.f;

    const size_t wz = (size_t)3 * HID * HID;
    tc_mainloop(g_ahi, g_alo, g_Whi + wz, g_Wlo + wz, m0, n0, smg, acc);

    const int tid = threadIdx.x, lane = tid & 31, wid = tid >> 5;
    const int warp_m = wid >> 1, warp_n = wid & 1;
    const int g = lane >> 2, c = lane & 3;
    const int wb = warp_n * 32;

    #pragma unroll
    for (int i = 0; i < 2; i++) {
        #pragma unroll
        for (int rh = 0; rh < 2; rh++) {
            int rm = m0 + warp_m * 32 + 16 * i + g + 8 * rh;
            #pragma unroll
            for (int j = 0; j < 8; j++) {
                #pragma unroll
                for (int d = 0; d < 2; d++) {
                    int col = n0 + wb + (j & 3) * 8 + (j >> 2) * 64 + 2 * c + d;
                    out[(size_t)rm * HID + col] = acc[i][j][rh * 2 + d] + bO[col];
                }
            }
        }
    }
}

// ---------------- sliding-window flash attention ----------------------------
#define QS_OFF 0
#define VS_OFF 8192
#define KS_OFF 16384            // 64 x 33
#define PS_OFF 18496            // 64 x 65
#define ATT_SMEM_BYTES ((18496 + 64*65) * 4)

__global__ __launch_bounds__(256) void attn_kernel(const float* __restrict__ kw) {
    extern __shared__ float sm[];
    float* Qs = sm + QS_OFF;
    float* Vs = sm + VS_OFF;
    float* Ks = sm + KS_OFF;
    float* Ps = sm + PS_OFF;

    const int tid = threadIdx.x;
    const int tx = tid & 15, ty = tid >> 4;
    const int q0 = blockIdx.x * 64;
    const int h  = blockIdx.y, b = blockIdx.z;

    const size_t base = (size_t)(b * NH + h) * SEQ * HD;
    const float* Qg = g_Q + base + (size_t)q0 * HD;
    const float* Kg = g_K + base;
    const float* Vg = g_V + base;

    #pragma unroll
    for (int t = 0; t < 8; t++) {
        int f = tid + t * 256;
        *(float4*)&Qs[f * 4] = *(const float4*)&Qg[f * 4];
    }

    const float mult = 0.08838834764831845f * kw[h];

    float O[4][8];
    #pragma unroll
    for (int i = 0; i < 4; i++)
        #pragma unroll
        for (int j = 0; j < 8; j++) O[i][j] = 0.f;
    float mrow[4], lrow[4];
    #pragma unroll
    for (int i = 0; i < 4; i++) { mrow[i] = -1e30f; lrow[i] = 0.f; }

    const int kt_lo = (q0 >= WIN) ? ((q0 - WIN) >> 6) : 0;
    const int kt_hi = q0 >> 6;

    for (int kt = kt_lo; kt <= kt_hi; kt++) {
        const int k0 = kt * 64;
        __syncthreads();
        #pragma unroll
        for (int t = 0; t < 8; t++) {
            int f = tid + t * 256;
            *(float4*)&Vs[f * 4] = *(const float4*)&Vg[(size_t)k0 * HD + f * 4];
        }

        float S[4][4];
        #pragma unroll
        for (int i = 0; i < 4; i++)
            #pragma unroll
            for (int jj = 0; jj < 4; jj++) S[i][jj] = 0.f;

        #pragma unroll
        for (int dc = 0; dc < 4; dc++) {
            #pragma unroll
            for (int t = 0; t < 2; t++) {
                int f = tid + t * 256;
                int r = f >> 3, c4 = (f & 7) * 4;
                float4 v = *(const float4*)&Kg[(size_t)(k0 + r) * HD + dc * 32 + c4];
                float* kp = &Ks[r * 33 + c4];
                kp[0] = v.x; kp[1] = v.y; kp[2] = v.z; kp[3] = v.w;
            }
            __syncthreads();
            #pragma unroll
            for (int d = 0; d < 32; d++) {
                float ra[4], rb[4];
                #pragma unroll
                for (int i = 0; i < 4; i++)  ra[i]  = Qs[(ty * 4 + i) * HD + dc * 32 + d];
                #pragma unroll
                for (int jj = 0; jj < 4; jj++) rb[jj] = Ks[(tx + 16 * jj) * 33 + d];
                #pragma unroll
                for (int i = 0; i < 4; i++)
                    #pragma unroll
                    for (int jj = 0; jj < 4; jj++)
                        S[i][jj] = fmaf(ra[i], rb[jj], S[i][jj]);
            }
            __syncthreads();
        }

        #pragma unroll
        for (int i = 0; i < 4; i++) {
            int qi = q0 + ty * 4 + i;
            float mloc = -1e30f;
            #pragma unroll
            for (int jj = 0; jj < 4; jj++) {
                int kj = k0 + tx + 16 * jj;
                float sv = S[i][jj] * mult;
                sv = (kj <= qi && kj + WIN >= qi) ? sv : -1e30f;
                S[i][jj] = sv;
                mloc = fmaxf(mloc, sv);
            }
            #pragma unroll
            for (int msk = 8; msk >= 1; msk >>= 1)
                mloc = fmaxf(mloc, __shfl_xor_sync(0xffffffffu, mloc, msk));
            float mnew = fmaxf(mrow[i], mloc);
            float corr = expf(mrow[i] - mnew);
            float psum = 0.f;
            #pragma unroll
            for (int jj = 0; jj < 4; jj++) {
                float p = expf(S[i][jj] - mnew);
                Ps[(ty * 4 + i) * 65 + tx + 16 * jj] = p;
                psum += p;
            }
            #pragma unroll
            for (int msk = 8; msk >= 1; msk >>= 1)
                psum += __shfl_xor_sync(0xffffffffu, psum, msk);
            lrow[i] = lrow[i] * corr + psum;
            mrow[i] = mnew;
            #pragma unroll
            for (int j = 0; j < 8; j++) O[i][j] *= corr;
        }
        __syncthreads();

        #pragma unroll 4
        for (int k = 0; k < 64; k++) {
            float rp[4], rv[8];
            #pragma unroll
            for (int i = 0; i < 4; i++) rp[i] = Ps[(ty * 4 + i) * 65 + k];
            #pragma unroll
            for (int j = 0; j < 8; j++) rv[j] = Vs[k * HD + tx + 16 * j];
            #pragma unroll
            for (int i = 0; i < 4; i++)
                #pragma unroll
                for (int j = 0; j < 8; j++)
                    O[i][j] = fmaf(rp[i], rv[j], O[i][j]);
        }
    }

    // epilogue: write attn output pre-split into bf16 hi/lo (feeds out GEMM)
    #pragma unroll
    for (int i = 0; i < 4; i++) {
        int qi = q0 + ty * 4 + i;
        float inv = 1.f / lrow[i];
        size_t row = ((size_t)b * SEQ + qi) * HID + h * HD;
        #pragma unroll
        for (int j = 0; j < 8; j++) {
            float v = O[i][j] * inv;
            __nv_bfloat16 hh = __float2bfloat16(v);
            __nv_bfloat16 ll = __float2bfloat16(v - __bfloat162float(hh));
            g_ahi[row + tx + 16 * j] = hh;
            g_alo[row + tx + 16 * j] = ll;
        }
    }
}

// ---------------- launch -----------------------------------------------------
extern "C" void kernel_launch(void* const* d_in, const int* in_sizes, int n_in,
                              void* d_out, int out_size) {
    const float* x  = (const float*)d_in[0];
    const float* WQ = (const float*)d_in[1];
    const float* bQ = (const float*)d_in[2];
    const float* WK = (const float*)d_in[3];
    const float* bK = (const float*)d_in[4];
    const float* WV = (const float*)d_in[5];
    const float* bV = (const float*)d_in[6];
    const float* WO = (const float*)d_in[7];
    const float* bO = (const float*)d_in[8];
    const float* kw = (const float*)d_in[9];
    float* out = (float*)d_out;

    rope_tab_kernel<<<(SEQ * 64 + 255) / 256, 256>>>();

    // resolve device-global scratch addresses (host side, graph-safe)
    static __nv_bfloat16 *xhi = nullptr, *xlo = nullptr, *whi = nullptr, *wlo = nullptr;
    if (!xhi) {
        cudaGetSymbolAddress((void**)&xhi, g_xhi);
        cudaGetSymbolAddress((void**)&xlo, g_xlo);
        cudaGetSymbolAddress((void**)&whi, g_Whi);
        cudaGetSymbolAddress((void**)&wlo, g_Wlo);
    }

    const int n4x = MTOT * HID / 4;
    const int n4w = HID * HID / 4;
    split_kernel<<<(n4x + 255) / 256, 256>>>(x,  xhi, xlo, n4x);
    split_kernel<<<(n4w + 255) / 256, 256>>>(WQ, whi + 0ull * HID * HID, wlo + 0ull * HID * HID, n4w);
    split_kernel<<<(n4w + 255) / 256, 256>>>(WK, whi + 1ull * HID * HID, wlo + 1ull * HID * HID, n4w);
    split_kernel<<<(n4w + 255) / 256, 256>>>(WV, whi + 2ull * HID * HID, wlo + 2ull * HID * HID, n4w);
    split_kernel<<<(n4w + 255) / 256, 256>>>(WO, whi + 3ull * HID * HID, wlo + 3ull * HID * HID, n4w);

    cudaFuncSetAttribute(qkv_tc_kernel, cudaFuncAttributeMaxDynamicSharedMemorySize,
                         GEMM_SMEM_BYTES);
    cudaFuncSetAttribute(out_tc_kernel, cudaFuncAttributeMaxDynamicSharedMemorySize,
                         GEMM_SMEM_BYTES);

    dim3 gq(NH, MTOT / 128, 3);
    qkv_tc_kernel<<<gq, 256, GEMM_SMEM_BYTES>>>(bQ, bK, bV);

    cudaFuncSetAttribute(attn_kernel, cudaFuncAttributeMaxDynamicSharedMemorySize,
                         ATT_SMEM_BYTES);
    attn_kernel<<<dim3(SEQ / 64, NH, BATCH), 256, ATT_SMEM_BYTES>>>(kw);

    out_tc_kernel<<<dim3(HID / 128, MTOT / 128), 256, GEMM_SMEM_BYTES>>>(bO, out);
}

// round 10
// speedup vs baseline: 2.1622x; 1.0490x over previous
#include <cuda_runtime.h>
#include <cuda_bf16.h>
#include <math.h>

#define SEQ    2048
#define HID    2048
#define NH     16
#define HD     128
#define BATCH  2
#define WIN    256
#define MTOT   (BATCH*SEQ)

// ---------------- scratch (static device globals; no allocations) -----------
__device__ float  g_Q[BATCH*NH*SEQ*HD];      // [B,H,S,D]
__device__ float  g_K[BATCH*NH*SEQ*HD];
__device__ float  g_V[BATCH*NH*SEQ*HD];
__device__ __nv_bfloat16 g_xhi[MTOT*HID], g_xlo[MTOT*HID];     // split x
__device__ __nv_bfloat16 g_Whi[4ull*HID*HID], g_Wlo[4ull*HID*HID]; // split W (K,N)
__device__ __nv_bfloat16 g_ahi[MTOT*HID], g_alo[MTOT*HID];     // split attn out
__device__ float2 g_rope[SEQ*64];

// ---------------- RoPE table -------------------------------------------------
__global__ void rope_tab_kernel() {
    int idx = blockIdx.x * blockDim.x + threadIdx.x;
    if (idx >= SEQ * 64) return;
    int s = idx >> 6, j = idx & 63;
    float invf = (float)pow(10000.0, -(double)j / 64.0);
    float ang  = (float)s * invf;
    double a   = (double)ang;
    g_rope[idx] = make_float2((float)cos(a), (float)sin(a));
}

// ---------------- fp32 -> bf16 hi/lo split -----------------------------------
__global__ void split_kernel(const float* __restrict__ in,
                             __nv_bfloat16* __restrict__ hi,
                             __nv_bfloat16* __restrict__ lo, int n4) {
    int i = blockIdx.x * blockDim.x + threadIdx.x;
    if (i >= n4) return;
    float4 f = ((const float4*)in)[i];
    float v[4] = {f.x, f.y, f.z, f.w};
    unsigned h[2], l[2];
    #pragma unroll
    for (int p = 0; p < 2; p++) {
        __nv_bfloat16 h0 = __float2bfloat16(v[2*p]);
        __nv_bfloat16 h1 = __float2bfloat16(v[2*p+1]);
        __nv_bfloat16 l0 = __float2bfloat16(v[2*p]   - __bfloat162float(h0));
        __nv_bfloat16 l1 = __float2bfloat16(v[2*p+1] - __bfloat162float(h1));
        __nv_bfloat162 hh = __halves2bfloat162(h0, h1);
        __nv_bfloat162 ll = __halves2bfloat162(l0, l1);
        h[p] = *(unsigned*)&hh; l[p] = *(unsigned*)&ll;
    }
    *(uint2*)(hi + 4 * (size_t)i) = make_uint2(h[0], h[1]);
    *(uint2*)(lo + 4 * (size_t)i) = make_uint2(l[0], l[1]);
}

// ---------------- tensor-core helpers ---------------------------------------
__device__ __forceinline__ unsigned smem_u32(const void* p) {
    return (unsigned)__cvta_generic_to_shared(p);
}
__device__ __forceinline__ void ldsm_x4(unsigned &r0, unsigned &r1,
                                        unsigned &r2, unsigned &r3, unsigned a) {
    asm volatile("ldmatrix.sync.aligned.m8n8.x4.shared.b16 {%0,%1,%2,%3},[%4];"
                 : "=r"(r0), "=r"(r1), "=r"(r2), "=r"(r3) : "r"(a));
}
__device__ __forceinline__ void ldsm_x4_t(unsigned &r0, unsigned &r1,
                                          unsigned &r2, unsigned &r3, unsigned a) {
    asm volatile("ldmatrix.sync.aligned.m8n8.x4.trans.shared.b16 {%0,%1,%2,%3},[%4];"
                 : "=r"(r0), "=r"(r1), "=r"(r2), "=r"(r3) : "r"(a));
}
__device__ __forceinline__ void mma16816(float* c, const unsigned* a, const unsigned* b) {
    asm volatile(
        "mma.sync.aligned.m16n8k16.row.col.f32.bf16.bf16.f32 "
        "{%0,%1,%2,%3},{%4,%5,%6,%7},{%8,%9},{%0,%1,%2,%3};"
        : "+f"(c[0]), "+f"(c[1]), "+f"(c[2]), "+f"(c[3])
        : "r"(a[0]), "r"(a[1]), "r"(a[2]), "r"(a[3]), "r"(b[0]), "r"(b[1]));
}
__device__ __forceinline__ void cp16(unsigned s, const void* g) {
    asm volatile("cp.async.cg.shared.global [%0], [%1], 16;" :: "r"(s), "l"(g));
}
__device__ __forceinline__ void cp_commit() { asm volatile("cp.async.commit_group;"); }
__device__ __forceinline__ void cp_wait1()  { asm volatile("cp.async.wait_group 1;"); }

// smem geometry (bf16 units); conflict-free for LDSM / LDSM.T
#define ASTR 40                 // 256 rows x 32 k, 80B rows
#define BSTR 136                // 32 k-rows x 128 n, 272B rows
#define STAGES 3
#define A_ONE   (256*ASTR)      // one matrix (hi or lo): 10240
#define A_STAGE (2*A_ONE)
#define B_ONE   (32*BSTR)       // 4352
#define B_STAGE (2*B_ONE)
#define B_BASE  (STAGES*A_STAGE)
#define GEMM_SMEM_BF16 (B_BASE + STAGES*B_STAGE)
#define GEMM_SMEM_BYTES (GEMM_SMEM_BF16*2)   // 175104

// C[256x128] = A[256xK] * B[Kx128]; split-bf16 3-pass, fp32 accumulate.
// 8 warps: 4 m-warps x 2 n-warps; warp tile 64x64, n interleave
// {0,8,16,24}∪{64,72,80,88} + warp_n*32 so RoPE pairs stay in-thread.
__device__ __forceinline__ void tc_mainloop(
    const __nv_bfloat16* __restrict__ Ahi_g, const __nv_bfloat16* __restrict__ Alo_g,
    const __nv_bfloat16* __restrict__ Bhi_g, const __nv_bfloat16* __restrict__ Blo_g,
    int m0, int n0, __nv_bfloat16* sm, float acc[4][8][4])
{
    const int tid = threadIdx.x;
    const int lane = tid & 31, wid = tid >> 5;
    const int warp_m = wid >> 1, warp_n = wid & 1;
    const unsigned smB = smem_u32(sm);

    const int NT = HID / 32;

    auto issue = [&](int slot, int kt) {
        unsigned sa = smB + (slot * A_STAGE) * 2;
        unsigned sb = smB + (B_BASE + slot * B_STAGE) * 2;
        const __nv_bfloat16* Ah = Ahi_g + (size_t)m0 * HID + kt * 32;
        const __nv_bfloat16* Al = Alo_g + (size_t)m0 * HID + kt * 32;
        const __nv_bfloat16* Bh = Bhi_g + (size_t)(kt * 32) * HID + n0;
        const __nv_bfloat16* Bl = Blo_g + (size_t)(kt * 32) * HID + n0;
        #pragma unroll
        for (int i = 0; i < 4; i++) {               // A: 4 chunks per matrix
            int id = tid + i * 256;
            int r = id >> 2, c8 = (id & 3) * 8;
            cp16(sa + (r * ASTR + c8) * 2,         Ah + (size_t)r * HID + c8);
            cp16(sa + (A_ONE + r * ASTR + c8) * 2, Al + (size_t)r * HID + c8);
        }
        #pragma unroll
        for (int i = 0; i < 2; i++) {               // B: 2 chunks per matrix
            int id = tid + i * 256;
            int r = id >> 4, c8 = (id & 15) * 8;
            cp16(sb + (r * BSTR + c8) * 2,         Bh + (size_t)r * HID + c8);
            cp16(sb + (B_ONE + r * BSTR + c8) * 2, Bl + (size_t)r * HID + c8);
        }
    };

    const int arow  = warp_m * 64 + (lane & 15);
    const int acol8 = (lane >> 4) * 8;
    const int brow  = lane & 15;
    const int bcol  = warp_n * 32 + (lane >> 4) * 8;

    #pragma unroll
    for (int s = 0; s < STAGES - 1; s++) { issue(s, s); cp_commit(); }

    for (int kt = 0; kt < NT; kt++) {
        cp_wait1();
        __syncthreads();
        if (kt + STAGES - 1 < NT) issue((kt + STAGES - 1) % STAGES, kt + STAGES - 1);
        cp_commit();

        const int slot = kt % STAGES;
        unsigned aHiB = smB + (slot * A_STAGE) * 2;
        unsigned aLoB = aHiB + A_ONE * 2;
        unsigned bHiB = smB + (B_BASE + slot * B_STAGE) * 2;
        unsigned bLoB = bHiB + B_ONE * 2;

        #pragma unroll
        for (int kb = 0; kb < 32; kb += 16) {
            unsigned bh[8][2], bl[8][2];
            #pragma unroll
            for (int p = 0; p < 4; p++) {
                int nOff = (p & 1) * 16 + (p >> 1) * 64;
                unsigned off = (unsigned)(((kb + brow) * BSTR + bcol + nOff) * 2);
                unsigned r0, r1, r2, r3;
                ldsm_x4_t(r0, r1, r2, r3, bHiB + off);
                bh[2*p][0] = r0; bh[2*p][1] = r1; bh[2*p+1][0] = r2; bh[2*p+1][1] = r3;
                ldsm_x4_t(r0, r1, r2, r3, bLoB + off);
                bl[2*p][0] = r0; bl[2*p][1] = r1; bl[2*p+1][0] = r2; bl[2*p+1][1] = r3;
            }
            #pragma unroll
            for (int i = 0; i < 4; i++) {
                unsigned ah[4], al[4];
                unsigned off = (unsigned)(((arow + 16 * i) * ASTR + kb + acol8) * 2);
                ldsm_x4(ah[0], ah[1], ah[2], ah[3], aHiB + off);
                ldsm_x4(al[0], al[1], al[2], al[3], aLoB + off);
                #pragma unroll
                for (int j = 0; j < 8; j++) {
                    mma16816(acc[i][j], ah, bh[j]);
                    mma16816(acc[i][j], ah, bl[j]);
                    mma16816(acc[i][j], al, bh[j]);
                }
            }
        }
        __syncthreads();
    }
}

// ---------------- fused QKV GEMM (+bias, +RoPE for Q/K, BHSD epilogue) ------
__global__ __launch_bounds__(256, 1) void qkv_tc_kernel(
    const float* __restrict__ bQ, const float* __restrict__ bK,
    const float* __restrict__ bV)
{
    extern __shared__ __align__(16) __nv_bfloat16 smg[];
    const int z = blockIdx.z;
    const float* bias = (z == 0) ? bQ : ((z == 1) ? bK : bV);
    const int m0 = blockIdx.y * 256, n0 = blockIdx.x * 128;

    float acc[4][8][4];
    #pragma unroll
    for (int i = 0; i < 4; i++)
        #pragma unroll
        for (int j = 0; j < 8; j++)
            #pragma unroll
            for (int r = 0; r < 4; r++) acc[i][j][r] = 0.f;

    const size_t wz = (size_t)z * HID * HID;
    tc_mainloop(g_xhi, g_xlo, g_Whi + wz, g_Wlo + wz, m0, n0, smg, acc);

    const int tid = threadIdx.x, lane = tid & 31, wid = tid >> 5;
    const int warp_m = wid >> 1, warp_n = wid & 1;
    const int g = lane >> 2, c = lane & 3;
    const int wb = warp_n * 32;
    const int h = blockIdx.x;                 // N-tile == one head
    float* out = (z == 0) ? g_Q : ((z == 1) ? g_K : g_V);

    #pragma unroll
    for (int i = 0; i < 4; i++) {
        #pragma unroll
        for (int rh = 0; rh < 2; rh++) {
            int rm = m0 + warp_m * 64 + 16 * i + g + 8 * rh;
            int bb = rm >> 11, s = rm & (SEQ - 1);
            float* orow = out + ((size_t)(bb * NH + h) * SEQ + s) * HD;
            if (z < 2) {
                #pragma unroll
                for (int j = 0; j < 4; j++) {
                    #pragma unroll
                    for (int d = 0; d < 2; d++) {
                        int reg = rh * 2 + d;
                        int d1  = wb + 8 * j + 2 * c + d;       // < 64
                        float t1 = acc[i][j][reg]     + bias[n0 + d1];
                        float t2 = acc[i][j + 4][reg] + bias[n0 + d1 + 64];
                        float2 cs = g_rope[s * 64 + d1];
                        orow[d1]      = t1 * cs.x - t2 * cs.y;
                        orow[d1 + 64] = t1 * cs.y + t2 * cs.x;
                    }
                }
            } else {
                #pragma unroll
                for (int j = 0; j < 8; j++) {
                    #pragma unroll
                    for (int d = 0; d < 2; d++) {
                        int col = wb + (j & 3) * 8 + (j >> 2) * 64 + 2 * c + d;
                        orow[col] = acc[i][j][rh * 2 + d] + bias[n0 + col];
                    }
                }
            }
        }
    }
}

// ---------------- output projection GEMM (+bias) ----------------------------
__global__ __launch_bounds__(256, 1) void out_tc_kernel(
    const float* __restrict__ bO, float* __restrict__ out)
{
    extern __shared__ __align__(16) __nv_bfloat16 smg[];
    const int m0 = blockIdx.y * 256, n0 = blockIdx.x * 128;

    float acc[4][8][4];
    #pragma unroll
    for (int i = 0; i < 4; i++)
        #pragma unroll
        for (int j = 0; j < 8; j++)
            #pragma unroll
            for (int r = 0; r < 4; r++) acc[i][j][r] = 0.f;

    const size_t wz = (size_t)3 * HID * HID;
    tc_mainloop(g_ahi, g_alo, g_Whi + wz, g_Wlo + wz, m0, n0, smg, acc);

    const int tid = threadIdx.x, lane = tid & 31, wid = tid >> 5;
    const int warp_m = wid >> 1, warp_n = wid & 1;
    const int g = lane >> 2, c = lane & 3;
    const int wb = warp_n * 32;

    #pragma unroll
    for (int i = 0; i < 4; i++) {
        #pragma unroll
        for (int rh = 0; rh < 2; rh++) {
            int rm = m0 + warp_m * 64 + 16 * i + g + 8 * rh;
            #pragma unroll
            for (int j = 0; j < 8; j++) {
                #pragma unroll
                for (int d = 0; d < 2; d++) {
                    int col = n0 + wb + (j & 3) * 8 + (j >> 2) * 64 + 2 * c + d;
                    out[(size_t)rm * HID + col] = acc[i][j][rh * 2 + d] + bO[col];
                }
            }
        }
    }
}

// ---------------- sliding-window flash attention ----------------------------
#define QS_OFF 0
#define VS_OFF 8192
#define KS_OFF 16384            // 64 x 33
#define PS_OFF 18496            // 64 x 65
#define ATT_SMEM_BYTES ((18496 + 64*65) * 4)

__global__ __launch_bounds__(256) void attn_kernel(const float* __restrict__ kw) {
    extern __shared__ float sm[];
    float* Qs = sm + QS_OFF;
    float* Vs = sm + VS_OFF;
    float* Ks = sm + KS_OFF;
    float* Ps = sm + PS_OFF;

    const int tid = threadIdx.x;
    const int tx = tid & 15, ty = tid >> 4;
    const int q0 = blockIdx.x * 64;
    const int h  = blockIdx.y, b = blockIdx.z;

    const size_t base = (size_t)(b * NH + h) * SEQ * HD;
    const float* Qg = g_Q + base + (size_t)q0 * HD;
    const float* Kg = g_K + base;
    const float* Vg = g_V + base;

    #pragma unroll
    for (int t = 0; t < 8; t++) {
        int f = tid + t * 256;
        *(float4*)&Qs[f * 4] = *(const float4*)&Qg[f * 4];
    }

    const float mult = 0.08838834764831845f * kw[h];

    float O[4][8];
    #pragma unroll
    for (int i = 0; i < 4; i++)
        #pragma unroll
        for (int j = 0; j < 8; j++) O[i][j] = 0.f;
    float mrow[4], lrow[4];
    #pragma unroll
    for (int i = 0; i < 4; i++) { mrow[i] = -1e30f; lrow[i] = 0.f; }

    const int kt_lo = (q0 >= WIN) ? ((q0 - WIN) >> 6) : 0;
    const int kt_hi = q0 >> 6;

    for (int kt = kt_lo; kt <= kt_hi; kt++) {
        const int k0 = kt * 64;
        __syncthreads();
        #pragma unroll
        for (int t = 0; t < 8; t++) {
            int f = tid + t * 256;
            *(float4*)&Vs[f * 4] = *(const float4*)&Vg[(size_t)k0 * HD + f * 4];
        }

        float S[4][4];
        #pragma unroll
        for (int i = 0; i < 4; i++)
            #pragma unroll
            for (int jj = 0; jj < 4; jj++) S[i][jj] = 0.f;

        #pragma unroll
        for (int dc = 0; dc < 4; dc++) {
            #pragma unroll
            for (int t = 0; t < 2; t++) {
                int f = tid + t * 256;
                int r = f >> 3, c4 = (f & 7) * 4;
                float4 v = *(const float4*)&Kg[(size_t)(k0 + r) * HD + dc * 32 + c4];
                float* kp = &Ks[r * 33 + c4];
                kp[0] = v.x; kp[1] = v.y; kp[2] = v.z; kp[3] = v.w;
            }
            __syncthreads();
            #pragma unroll
            for (int d = 0; d < 32; d++) {
                float ra[4], rb[4];
                #pragma unroll
                for (int i = 0; i < 4; i++)  ra[i]  = Qs[(ty * 4 + i) * HD + dc * 32 + d];
                #pragma unroll
                for (int jj = 0; jj < 4; jj++) rb[jj] = Ks[(tx + 16 * jj) * 33 + d];
                #pragma unroll
                for (int i = 0; i < 4; i++)
                    #pragma unroll
                    for (int jj = 0; jj < 4; jj++)
                        S[i][jj] = fmaf(ra[i], rb[jj], S[i][jj]);
            }
            __syncthreads();
        }

        #pragma unroll
        for (int i = 0; i < 4; i++) {
            int qi = q0 + ty * 4 + i;
            float mloc = -1e30f;
            #pragma unroll
            for (int jj = 0; jj < 4; jj++) {
                int kj = k0 + tx + 16 * jj;
                float sv = S[i][jj] * mult;
                sv = (kj <= qi && kj + WIN >= qi) ? sv : -1e30f;
                S[i][jj] = sv;
                mloc = fmaxf(mloc, sv);
            }
            #pragma unroll
            for (int msk = 8; msk >= 1; msk >>= 1)
                mloc = fmaxf(mloc, __shfl_xor_sync(0xffffffffu, mloc, msk));
            float mnew = fmaxf(mrow[i], mloc);
            float corr = expf(mrow[i] - mnew);
            float psum = 0.f;
            #pragma unroll
            for (int jj = 0; jj < 4; jj++) {
                float p = expf(S[i][jj] - mnew);
                Ps[(ty * 4 + i) * 65 + tx + 16 * jj] = p;
                psum += p;
            }
            #pragma unroll
            for (int msk = 8; msk >= 1; msk >>= 1)
                psum += __shfl_xor_sync(0xffffffffu, psum, msk);
            lrow[i] = lrow[i] * corr + psum;
            mrow[i] = mnew;
            #pragma unroll
            for (int j = 0; j < 8; j++) O[i][j] *= corr;
        }
        __syncthreads();

        #pragma unroll 4
        for (int k = 0; k < 64; k++) {
            float rp[4], rv[8];
            #pragma unroll
            for (int i = 0; i < 4; i++) rp[i] = Ps[(ty * 4 + i) * 65 + k];
            #pragma unroll
            for (int j = 0; j < 8; j++) rv[j] = Vs[k * HD + tx + 16 * j];
            #pragma unroll
            for (int i = 0; i < 4; i++)
                #pragma unroll
                for (int j = 0; j < 8; j++)
                    O[i][j] = fmaf(rp[i], rv[j], O[i][j]);
        }
    }

    // epilogue: pre-split bf16 hi/lo for the output GEMM
    #pragma unroll
    for (int i = 0; i < 4; i++) {
        int qi = q0 + ty * 4 + i;
        float inv = 1.f / lrow[i];
        size_t row = ((size_t)b * SEQ + qi) * HID + h * HD;
        #pragma unroll
        for (int j = 0; j < 8; j++) {
            float v = O[i][j] * inv;
            __nv_bfloat16 hh = __float2bfloat16(v);
            __nv_bfloat16 ll = __float2bfloat16(v - __bfloat162float(hh));
            g_ahi[row + tx + 16 * j] = hh;
            g_alo[row + tx + 16 * j] = ll;
        }
    }
}

// ---------------- launch -----------------------------------------------------
extern "C" void kernel_launch(void* const* d_in, const int* in_sizes, int n_in,
                              void* d_out, int out_size) {
    const float* x  = (const float*)d_in[0];
    const float* WQ = (const float*)d_in[1];
    const float* bQ = (const float*)d_in[2];
    const float* WK = (const float*)d_in[3];
    const float* bK = (const float*)d_in[4];
    const float* WV = (const float*)d_in[5];
    const float* bV = (const float*)d_in[6];
    const float* WO = (const float*)d_in[7];
    const float* bO = (const float*)d_in[8];
    const float* kw = (const float*)d_in[9];
    float* out = (float*)d_out;

    static __nv_bfloat16 *xhi = nullptr, *xlo = nullptr, *whi = nullptr, *wlo = nullptr;
    static bool attr_set = false;
    if (!xhi) {
        cudaGetSymbolAddress((void**)&xhi, g_xhi);
        cudaGetSymbolAddress((void**)&xlo, g_xlo);
        cudaGetSymbolAddress((void**)&whi, g_Whi);
        cudaGetSymbolAddress((void**)&wlo, g_Wlo);
    }
    if (!attr_set) {
        cudaFuncSetAttribute(qkv_tc_kernel, cudaFuncAttributeMaxDynamicSharedMemorySize, GEMM_SMEM_BYTES);
        cudaFuncSetAttribute(out_tc_kernel, cudaFuncAttributeMaxDynamicSharedMemorySize, GEMM_SMEM_BYTES);
        cudaFuncSetAttribute(attn_kernel,   cudaFuncAttributeMaxDynamicSharedMemorySize, ATT_SMEM_BYTES);
        attr_set = true;
    }

    rope_tab_kernel<<<(SEQ * 64 + 255) / 256, 256>>>();

    const int n4x = MTOT * HID / 4;
    const int n4w = HID * HID / 4;
    split_kernel<<<(n4x + 255) / 256, 256>>>(x,  xhi, xlo, n4x);
    split_kernel<<<(n4w + 255) / 256, 256>>>(WQ, whi + 0ull * HID * HID, wlo + 0ull * HID * HID, n4w);
    split_kernel<<<(n4w + 255) / 256, 256>>>(WK, whi + 1ull * HID * HID, wlo + 1ull * HID * HID, n4w);
    split_kernel<<<(n4w + 255) / 256, 256>>>(WV, whi + 2ull * HID * HID, wlo + 2ull * HID * HID, n4w);
    split_kernel<<<(n4w + 255) / 256, 256>>>(WO, whi + 3ull * HID * HID, wlo + 3ull * HID * HID, n4w);

    dim3 gq(NH, MTOT / 256, 3);
    qkv_tc_kernel<<<gq, 256, GEMM_SMEM_BYTES>>>(bQ, bK, bV);

    attn_kernel<<<dim3(SEQ / 64, NH, BATCH), 256, ATT_SMEM_BYTES>>>(kw);

    out_tc_kernel<<<dim3(HID / 128, MTOT / 256), 256, GEMM_SMEM_BYTES>>>(bO, out);
}